// round 3
// baseline (speedup 1.0000x reference)
#include <cuda_runtime.h>
#include <math.h>

// ---------------- problem constants ----------------
#define T_STEPS 512
#define BATCH   128
#define HDIM    300
#define MCELLS  20
#define ROWS    (BATCH*MCELLS)   // 2560
#define DECAY   0.98f
#define EPS_V   1e-8f

#define NBLOCKS  148   // <= SM count on B300(148)/GB300(152): guaranteed co-resident
#define NTHREADS 256

// 1 = JAX >= 0.4.30 default (threefry_partitionable), 0 = legacy split-iota scheme
#define THREEFRY_PARTITIONABLE 1

// ---------------- device state (no allocation anywhere) ----------------
__device__ float g_mem[ROWS*HDIM];    // (B,M,H)
__device__ float g_usage[ROWS];       // (B,M)
__device__ float g_HP[ROWS*HDIM];     // mem@Ws1[0:300] + (h*mem)@Ws1[600:900]
__device__ float g_CP[ROWS*HDIM];     // mem@Wu[300:600]
__device__ float g_P[BATCH*900];      // [0:300]=h@We1 [300:600]=h@Ws1[300:600] [600:900]=h@Wu[0:300]
__device__ unsigned g_count;          // grid-barrier counter (memset to 0 per launch)

// ---------------- software grid barrier ----------------
__device__ __forceinline__ void grid_bar(unsigned &target) {
    __syncthreads();
    if (threadIdx.x == 0) {
        target += NBLOCKS;
        __threadfence();
        atomicAdd(&g_count, 1u);
        volatile unsigned* p = &g_count;
        while (*p < target) { }
        __threadfence();
    }
    __syncthreads();
}

// ---------------- JAX threefry-2x32-20 noise ----------------
__device__ __forceinline__ void tf_round(unsigned &x0, unsigned &x1, int r) {
    x0 += x1;
    x1 = (x1 << r) | (x1 >> (32 - r));
    x1 ^= x0;
}
__device__ __forceinline__ void threefry2x32(unsigned c0, unsigned c1,
                                             unsigned &o0, unsigned &o1) {
    const unsigned k0 = 0u, k1 = 42u, k2 = 0x1BD11BDAu ^ 0u ^ 42u;
    unsigned x0 = c0 + k0, x1 = c1 + k1;
    tf_round(x0,x1,13); tf_round(x0,x1,15); tf_round(x0,x1,26); tf_round(x0,x1,6);
    x0 += k1; x1 += k2 + 1u;
    tf_round(x0,x1,17); tf_round(x0,x1,29); tf_round(x0,x1,16); tf_round(x0,x1,24);
    x0 += k2; x1 += k0 + 2u;
    tf_round(x0,x1,13); tf_round(x0,x1,15); tf_round(x0,x1,26); tf_round(x0,x1,6);
    x0 += k0; x1 += k1 + 3u;
    tf_round(x0,x1,17); tf_round(x0,x1,29); tf_round(x0,x1,16); tf_round(x0,x1,24);
    x0 += k1; x1 += k2 + 4u;
    tf_round(x0,x1,13); tf_round(x0,x1,15); tf_round(x0,x1,26); tf_round(x0,x1,6);
    x0 += k2; x1 += k0 + 5u;
    o0 = x0; o1 = x1;
}
__device__ __forceinline__ float jax_noise(unsigned i) {
    unsigned bits;
#if THREEFRY_PARTITIONABLE
    unsigned o0, o1;
    threefry2x32(0u, i, o0, o1);     // counter = (hi32, lo32) of 64-bit index
    bits = o0 ^ o1;
#else
    const unsigned half = (unsigned)(T_STEPS*BATCH*MCELLS) / 2u;  // 655360
    unsigned o0, o1;
    if (i < half) { threefry2x32(i, i + half, o0, o1); bits = o0; }
    else          { threefry2x32(i - half, i, o0, o1); bits = o1; }
#endif
    float f = __uint_as_float((bits >> 9) | 0x3f800000u) - 1.0f;   // [0,1)
    float u = __fadd_rn(__fmul_rn(f, 0.99f), 0.01f);
    return fmaxf(0.01f, u);
}

// ---------------- warp reductions ----------------
__device__ __forceinline__ float warpSum(float v) {
#pragma unroll
    for (int o = 16; o; o >>= 1) v += __shfl_xor_sync(0xffffffffu, v, o);
    return v;
}
__device__ __forceinline__ float warpMax(float v) {
#pragma unroll
    for (int o = 16; o; o >>= 1) v = fmaxf(v, __shfl_xor_sync(0xffffffffu, v, o));
    return v;
}

// ---------------- GEMM tile job ----------------
// jobs   0..199 (mode 1): HP(2560x300) = [mem | h*mem](2560x600) @ [Ws1(0:300);Ws1(600:900)]
// jobs 200..399 (mode 2): CP(2560x300) = mem(2560x300) @ Wu(300:600)
// jobs 400..429 (mode 0): P  (128x900) = h(128x300) @ [We1 | Ws1(300:600) | Wu(0:300)]
#define BM 64
#define BN 64
#define BK 20

__device__ __forceinline__ void gemm_job(
    int blk, int t,
    const float* __restrict__ hs, const float* __restrict__ We1,
    const float* __restrict__ Ws1, const float* __restrict__ Wu,
    float (&As)[BK][BM+4], float (&Bs)[BK][BN])
{
    const int tid = threadIdx.x;
    int mode, rt, ct, role = 0;
    if (blk < 200)      { mode = 1; rt = blk/5; ct = blk%5; }
    else if (blk < 400) { mode = 2; int e = blk-200; rt = e/5; ct = e%5; }
    else { mode = 0; int e = blk-400; role = e/10; int r2 = e%10; rt = r2/5; ct = r2%5; }

    const int r0 = rt*BM, c0 = ct*BN;
    const int K  = (mode == 1) ? 600 : 300;
    const float* hbase = hs + (size_t)t * BATCH * HDIM;

    const int tx = tid & 15;   // 16 column groups of 4
    const int ty = tid >> 4;   // 16 row groups of 4
    float acc[4][4];
#pragma unroll
    for (int i = 0; i < 4; i++)
#pragma unroll
        for (int j = 0; j < 4; j++) acc[i][j] = 0.f;

    for (int k0 = 0; k0 < K; k0 += BK) {
        const bool hi = (k0 >= 300);   // uniform per tile (300 % BK == 0)
        // --- A tile: 64 rows x 20 k, stored transposed As[k][r] ---
#pragma unroll
        for (int i = 0; i < 5; i++) {
            int idx = tid + i*NTHREADS;
            int r = idx / BK, k = idx - r*BK;
            int rg = r0 + r, kg = k0 + k;
            float v;
            if (mode == 0)      v = hbase[rg*HDIM + kg];
            else if (!hi)       v = g_mem[rg*HDIM + kg];
            else { int kk = kg - 300;
                   v = g_mem[rg*HDIM + kk] * hbase[(rg/MCELLS)*HDIM + kk]; }
            As[k][r] = v;
        }
        // --- B tile: 20 k x 64 cols ---
#pragma unroll
        for (int i = 0; i < 5; i++) {
            int idx = tid + i*NTHREADS;
            int k = idx >> 6, j = idx & 63;
            int kg = k0 + k, jg = c0 + j;
            float v = 0.f;
            if (jg < 300) {
                if (mode == 1)      { int row = hi ? (kg + 300) : kg; v = Ws1[row*300 + jg]; }
                else if (mode == 2) { v = Wu[(kg + 300)*300 + jg]; }
                else {
                    if (role == 0)      v = We1[kg*300 + jg];
                    else if (role == 1) v = Ws1[(kg + 300)*300 + jg];
                    else                v = Wu[kg*300 + jg];
                }
            }
            Bs[k][j] = v;
        }
        __syncthreads();
#pragma unroll
        for (int k = 0; k < BK; k++) {
            float4 av = *(const float4*)&As[k][ty*4];
            float4 bv = *(const float4*)&Bs[k][tx*4];
            float a0 = av.x, a1 = av.y, a2 = av.z, a3 = av.w;
            acc[0][0] = fmaf(a0, bv.x, acc[0][0]); acc[0][1] = fmaf(a0, bv.y, acc[0][1]);
            acc[0][2] = fmaf(a0, bv.z, acc[0][2]); acc[0][3] = fmaf(a0, bv.w, acc[0][3]);
            acc[1][0] = fmaf(a1, bv.x, acc[1][0]); acc[1][1] = fmaf(a1, bv.y, acc[1][1]);
            acc[1][2] = fmaf(a1, bv.z, acc[1][2]); acc[1][3] = fmaf(a1, bv.w, acc[1][3]);
            acc[2][0] = fmaf(a2, bv.x, acc[2][0]); acc[2][1] = fmaf(a2, bv.y, acc[2][1]);
            acc[2][2] = fmaf(a2, bv.z, acc[2][2]); acc[2][3] = fmaf(a2, bv.w, acc[2][3]);
            acc[3][0] = fmaf(a3, bv.x, acc[3][0]); acc[3][1] = fmaf(a3, bv.y, acc[3][1]);
            acc[3][2] = fmaf(a3, bv.z, acc[3][2]); acc[3][3] = fmaf(a3, bv.w, acc[3][3]);
        }
        __syncthreads();
    }
#pragma unroll
    for (int i = 0; i < 4; i++) {
        int rg = r0 + ty*4 + i;
#pragma unroll
        for (int j = 0; j < 4; j++) {
            int jg = c0 + tx*4 + j;
            if (jg < 300) {
                if (mode == 1)      g_HP[rg*300 + jg] = acc[i][j];
                else if (mode == 2) g_CP[rg*300 + jg] = acc[i][j];
                else                g_P[rg*900 + role*300 + jg] = acc[i][j];
            }
        }
    }
}

// ---------------- gate + memory-update job (one block handles batch b) ----------------
__device__ __forceinline__ void gate_job(
    int b, int t,
    const float* __restrict__ hs, const float* __restrict__ mask,
    const float* __restrict__ be1, const float* __restrict__ We2,
    const float* __restrict__ be2, const float* __restrict__ bs1,
    const float* __restrict__ Ws2, const float* __restrict__ bs2,
    const float* __restrict__ Ws1, const float* __restrict__ bu,
    float* __restrict__ out,
    float (&s_sim)[MCELLS], float (&s_usage)[MCELLS],
    float (&s_indv)[MCELLS], float (&s_ow)[MCELLS],
    float (&s_red)[8], float &s_ent)
{
    const int tid = threadIdx.x;
    const int warp = tid >> 5, lane = tid & 31;

    const float* hb = hs + ((size_t)t*BATCH + b) * HDIM;
    const float* P  = g_P + b*900;
    const float* wu_row = Ws1 + 900*300;   // usage-feature row of Ws1

    if (tid < MCELLS) s_usage[tid] = g_usage[b*MCELLS + tid];
    __syncthreads();

    // ---- entity prob: sigmoid( relu(h@We1+be1) @ We2 + be2 ) * mask ----
    float acc = 0.f;
    for (int j = tid; j < 300; j += NTHREADS)
        acc += fmaxf(P[j] + be1[j], 0.f) * We2[j];
    acc = warpSum(acc);
    if (lane == 0) s_red[warp] = acc;
    __syncthreads();
    if (tid == 0) {
        float s = 0.f;
        for (int w = 0; w < 8; w++) s += s_red[w];
        float score = s + be2[0];
        float sig = 1.f / (1.f + expf(-score));
        s_ent = sig * mask[(size_t)t*BATCH + b];
    }

    // ---- sim[m] = relu(HP + h@Ws1_h + usage*wu_row + bs1) @ Ws2 + bs2 ----
    for (int m = warp; m < MCELLS; m += 8) {
        float u = s_usage[m];
        const float* HPr = g_HP + (b*MCELLS + m)*300;
        float a = 0.f;
        for (int j = lane; j < 300; j += 32)
            a += fmaxf(HPr[j] + P[300 + j] + u*wu_row[j] + bs1[j], 0.f) * Ws2[j];
        a = warpSum(a);
        if (lane == 0) s_sim[m] = a + bs2[0];
    }
    __syncthreads();

    // ---- gating (warp 0; lane = slot 0..20) ----
    if (warp == 0) {
        const unsigned FULL = 0xffffffffu;
        const int m = lane;
        const float NEG_INF = -INFINITY;
        float usg  = (m < MCELLS) ? s_usage[m] : 0.f;
        float simv = (m < MCELLS) ? s_sim[m]   : 0.f;

        float comb;
        if (m < MCELLS)       comb = (usg > 0.f) ? simv : -10000.f;
        else if (m == MCELLS) comb = 0.f;
        else                  comb = NEG_INF;
        float mx   = warpMax(comb);
        float ex   = (m <= MCELLS) ? expf(comb - mx) : 0.f;
        float esum = warpSum(ex);
        float prob = ex / esum;
        float mult = (m < MCELLS) ? ((usg > 0.f) ? 1.f : 0.f)
                                  : ((m == MCELLS) ? 1.f : 0.f);
        float maskedp = prob * mult;
        float msum = warpSum(maskedp);
        float nrm  = maskedp / (msum + EPS_V);
        float co   = s_ent * nrm;
        float ow_base = __shfl_sync(FULL, co, MCELLS);
        float indv = (m < MCELLS) ? co : 0.f;

        // nsim = softmax(sim) over the M cells
        float s2  = (m < MCELLS) ? simv : NEG_INF;
        float mx2 = warpMax(s2);
        float e2  = (m < MCELLS) ? expf(simv - mx2) : 0.f;
        float es2 = warpSum(e2);
        float nsim = e2 / es2;

        float ow_score = (m < MCELLS)
            ? ((usg == 0.f ? nsim * 100000.f : 0.f) + (1.f - usg))
            : NEG_INF;
        float maxv = warpMax(ow_score);
        float nz   = (m < MCELLS && ow_score == maxv)
            ? jax_noise((unsigned)(((size_t)t*BATCH + b)*MCELLS + m)) : 0.f;
        float nzmax = warpMax(nz);
        unsigned ballot = __ballot_sync(FULL, (m < MCELLS) && (nz == nzmax));
        int idx = __ffs(ballot) - 1;   // first index of max (JAX argmax semantics)

        float ow = (m == idx) ? ow_base : 0.f;
        float nu = fminf(1.f, ow + indv + DECAY * usg);

        float* out_ent = out;
        float* out_usg = out + (size_t)T_STEPS*BATCH;
        float* out_crf = out_usg + (size_t)T_STEPS*BATCH*MCELLS;
        float* out_ow  = out_crf + (size_t)T_STEPS*BATCH*MCELLS;
        if (m < MCELLS) {
            s_indv[m] = indv;
            s_ow[m]   = ow;
            g_usage[b*MCELLS + m] = nu;
            size_t o = ((size_t)t*BATCH + b)*MCELLS + m;
            out_usg[o] = nu;
            out_crf[o] = indv * (1.f - EPS_V) + EPS_V;
            out_ow[o]  = ow   * (1.f - EPS_V) + EPS_V;
        }
        if (m == 0)
            out_ent[(size_t)t*BATCH + b] = s_ent * (1.f - EPS_V) + EPS_V;
    }
    __syncthreads();

    // ---- memory update ----
    for (int m = 0; m < MCELLS; m++) {
        float owv = s_ow[m], iv = s_indv[m];
        float coef = 1.f - owv - iv;
        float* memr = g_mem + (b*MCELLS + m)*300;
        const float* CPr = g_CP + (b*MCELLS + m)*300;
        for (int j = tid; j < 300; j += NTHREADS) {
            float c = tanhf(CPr[j] + P[600 + j] + bu[j]);
            memr[j] = owv*hb[j] + coef*memr[j] + iv*c;
        }
    }
}

// ---------------- persistent kernel ----------------
__global__ __launch_bounds__(NTHREADS) void k_persist(
    const float* __restrict__ hs, const float* __restrict__ mask,
    const float* __restrict__ We1, const float* __restrict__ be1,
    const float* __restrict__ We2, const float* __restrict__ be2,
    const float* __restrict__ Ws1, const float* __restrict__ bs1,
    const float* __restrict__ Ws2, const float* __restrict__ bs2,
    const float* __restrict__ Wu,  const float* __restrict__ bu,
    float* __restrict__ out)
{
    __shared__ float As[BK][BM+4];
    __shared__ float Bs[BK][BN];
    __shared__ float s_sim[MCELLS], s_usage[MCELLS], s_indv[MCELLS], s_ow[MCELLS];
    __shared__ float s_red[8];
    __shared__ float s_ent;

    unsigned target = 0;
    for (int t = 0; t < T_STEPS; t++) {
        // phase A: GEMMs
        for (int job = blockIdx.x; job < 430; job += NBLOCKS)
            gemm_job(job, t, hs, We1, Ws1, Wu, As, Bs);
        grid_bar(target);
        // phase B: gate + memory update
        if (blockIdx.x < BATCH)
            gate_job(blockIdx.x, t, hs, mask, be1, We2, be2, bs1, Ws2, bs2,
                     Ws1, bu, out, s_sim, s_usage, s_indv, s_ow, s_red, s_ent);
        grid_bar(target);
    }
}

extern "C" void kernel_launch(void* const* d_in, const int* in_sizes, int n_in,
                              void* d_out, int out_size) {
    const float* hs   = (const float*)d_in[0];
    const float* mask = (const float*)d_in[1];
    const float* We1  = (const float*)d_in[2];
    const float* be1  = (const float*)d_in[3];
    const float* We2  = (const float*)d_in[4];
    const float* be2  = (const float*)d_in[5];
    const float* Ws1  = (const float*)d_in[6];
    const float* bs1  = (const float*)d_in[7];
    const float* Ws2  = (const float*)d_in[8];
    const float* bs2  = (const float*)d_in[9];
    const float* Wu   = (const float*)d_in[10];
    const float* bu   = (const float*)d_in[11];
    float* out = (float*)d_out;

    void *pmem, *pusg, *pcnt;
    cudaGetSymbolAddress(&pmem, g_mem);
    cudaGetSymbolAddress(&pusg, g_usage);
    cudaGetSymbolAddress(&pcnt, g_count);
    cudaMemsetAsync(pmem, 0, sizeof(float)*(size_t)ROWS*HDIM);
    cudaMemsetAsync(pusg, 0, sizeof(float)*(size_t)ROWS);
    cudaMemsetAsync(pcnt, 0, sizeof(unsigned));

    k_persist<<<NBLOCKS, NTHREADS>>>(hs, mask, We1, be1, We2, be2,
                                     Ws1, bs1, Ws2, bs2, Wu, bu, out);
}

// round 4
// speedup vs baseline: 1.6347x; 1.6347x over previous
#include <cuda_runtime.h>
#include <math.h>

// ---------------- problem constants ----------------
#define T_STEPS 512
#define BATCH   128
#define HDIM    300
#define MCELLS  20
#define ROWS    (BATCH*MCELLS)   // 2560
#define DECAY   0.98f
#define EPS_V   1e-8f

#define NBLOCKS  296   // 2 CTAs/SM on 148-SM B300 (GB300 has 152, still co-resident)
#define NTHREADS 256
#define NJOBS    630   // 200 HP_lo + 200 HP_hi + 200 CP + 30 P, all K=300

// 1 = JAX >= 0.4.30 default (threefry_partitionable)
#define THREEFRY_PARTITIONABLE 1

// ---------------- device state (no allocation anywhere) ----------------
__device__ float g_mem[ROWS*HDIM];     // (B,M,H)
__device__ float g_usage[ROWS];        // (B,M)
__device__ float g_HP [ROWS*HDIM];     // mem@Ws1[0:300]
__device__ float g_HP2[ROWS*HDIM];     // (h*mem)@Ws1[600:900]
__device__ float g_CP [ROWS*HDIM];     // mem@Wu[300:600]
__device__ float g_P[BATCH*900];       // h@[We1 | Ws1(300:600) | Wu(0:300)]
__device__ unsigned g_count;           // grid-barrier counter
__device__ unsigned g_jobctr[T_STEPS]; // per-step dynamic job counters

// ---------------- software grid barrier ----------------
__device__ __forceinline__ void grid_bar(unsigned &target) {
    __syncthreads();
    if (threadIdx.x == 0) {
        target += NBLOCKS;
        __threadfence();
        atomicAdd(&g_count, 1u);
        volatile unsigned* p = &g_count;
        while (*p < target) { }
        __threadfence();
    }
    __syncthreads();
}

// ---------------- JAX threefry-2x32-20 noise ----------------
__device__ __forceinline__ void tf_round(unsigned &x0, unsigned &x1, int r) {
    x0 += x1;
    x1 = (x1 << r) | (x1 >> (32 - r));
    x1 ^= x0;
}
__device__ __forceinline__ void threefry2x32(unsigned c0, unsigned c1,
                                             unsigned &o0, unsigned &o1) {
    const unsigned k0 = 0u, k1 = 42u, k2 = 0x1BD11BDAu ^ 0u ^ 42u;
    unsigned x0 = c0 + k0, x1 = c1 + k1;
    tf_round(x0,x1,13); tf_round(x0,x1,15); tf_round(x0,x1,26); tf_round(x0,x1,6);
    x0 += k1; x1 += k2 + 1u;
    tf_round(x0,x1,17); tf_round(x0,x1,29); tf_round(x0,x1,16); tf_round(x0,x1,24);
    x0 += k2; x1 += k0 + 2u;
    tf_round(x0,x1,13); tf_round(x0,x1,15); tf_round(x0,x1,26); tf_round(x0,x1,6);
    x0 += k0; x1 += k1 + 3u;
    tf_round(x0,x1,17); tf_round(x0,x1,29); tf_round(x0,x1,16); tf_round(x0,x1,24);
    x0 += k1; x1 += k2 + 4u;
    tf_round(x0,x1,13); tf_round(x0,x1,15); tf_round(x0,x1,26); tf_round(x0,x1,6);
    x0 += k2; x1 += k0 + 5u;
    o0 = x0; o1 = x1;
}
__device__ __forceinline__ float jax_noise(unsigned i) {
    unsigned bits;
#if THREEFRY_PARTITIONABLE
    unsigned o0, o1;
    threefry2x32(0u, i, o0, o1);
    bits = o0 ^ o1;
#else
    const unsigned half = (unsigned)(T_STEPS*BATCH*MCELLS) / 2u;
    unsigned o0, o1;
    if (i < half) { threefry2x32(i, i + half, o0, o1); bits = o0; }
    else          { threefry2x32(i - half, i, o0, o1); bits = o1; }
#endif
    float f = __uint_as_float((bits >> 9) | 0x3f800000u) - 1.0f;
    float u = __fadd_rn(__fmul_rn(f, 0.99f), 0.01f);
    return fmaxf(0.01f, u);
}

// ---------------- warp reductions ----------------
__device__ __forceinline__ float warpSum(float v) {
#pragma unroll
    for (int o = 16; o; o >>= 1) v += __shfl_xor_sync(0xffffffffu, v, o);
    return v;
}
__device__ __forceinline__ float warpMax(float v) {
#pragma unroll
    for (int o = 16; o; o >>= 1) v = fmaxf(v, __shfl_xor_sync(0xffffffffu, v, o));
    return v;
}

// ---------------- GEMM tile job (all jobs K=300, 15 k-tiles) ----------------
// job   0..199 : HP_lo = mem       @ Ws1[  0:300]  -> g_HP   (40 rt x 5 ct)
// job 200..399 : HP_hi = (h*mem)   @ Ws1[600:900]  -> g_HP2
// job 400..599 : CP    = mem       @ Wu [300:600]  -> g_CP
// job 600..629 : P     = h(128x300)@ [We1|Ws1m|Wu] -> g_P    (2 rt x 15 ct over 900 cols)
#define BM 64
#define BN 64
#define BK 20

__device__ __forceinline__ void gemm_job(
    int job, int t,
    const float* __restrict__ hs, const float* __restrict__ We1,
    const float* __restrict__ Ws1, const float* __restrict__ Wu,
    float (&As)[BK][BM+4], float (&Bs)[BK][BN])
{
    const int tid = threadIdx.x;
    const float* hbase = hs + (size_t)t * BATCH * HDIM;

    int mode, r0, c0;
    if (job < 600) {
        mode = job / 200;                 // 0=HP_lo 1=HP_hi 2=CP
        int e = job % 200;
        r0 = (e / 5) * BM;                // 40 row tiles over 2560
        c0 = (e % 5) * BN;                // 5 col tiles over 300
    } else {
        mode = 3;
        int e = job - 600;
        r0 = (e / 15) * BM;               // 2 row tiles over 128
        c0 = (e % 15) * BN;               // 15 col tiles over 900
    }
    const int ncols = (mode == 3) ? 900 : 300;

    const int tx = tid & 15;              // 16 col groups of 4
    const int ty = tid >> 4;              // 16 row groups of 4
    float acc[4][4];
#pragma unroll
    for (int i = 0; i < 4; i++)
#pragma unroll
        for (int j = 0; j < 4; j++) acc[i][j] = 0.f;

    for (int k0 = 0; k0 < 300; k0 += BK) {
        // --- A tile: 64 rows x 20 k, stored transposed As[k][r] ---
#pragma unroll
        for (int i = 0; i < 5; i++) {
            int idx = tid + i*NTHREADS;
            int r = idx / BK, k = idx - r*BK;
            int rg = r0 + r, kg = k0 + k;
            float v;
            if (mode == 0 || mode == 2)      v = g_mem[rg*HDIM + kg];
            else if (mode == 1)              v = g_mem[rg*HDIM + kg] *
                                                 hbase[(rg/MCELLS)*HDIM + kg];
            else                             v = hbase[rg*HDIM + kg];
            As[k][r] = v;
        }
        // --- B tile: 20 k x 64 cols ---
#pragma unroll
        for (int i = 0; i < 5; i++) {
            int idx = tid + i*NTHREADS;
            int k = idx >> 6, j = idx & 63;
            int kg = k0 + k, jg = c0 + j;
            float v = 0.f;
            if (jg < ncols) {
                if (mode == 0)      v = Ws1[kg*300 + jg];
                else if (mode == 1) v = Ws1[(kg + 600)*300 + jg];
                else if (mode == 2) v = Wu[(kg + 300)*300 + jg];
                else {
                    int role = jg / 300, jc = jg - role*300;
                    if (role == 0)      v = We1[kg*300 + jc];
                    else if (role == 1) v = Ws1[(kg + 300)*300 + jc];
                    else                v = Wu[kg*300 + jc];
                }
            }
            Bs[k][j] = v;
        }
        __syncthreads();
#pragma unroll
        for (int k = 0; k < BK; k++) {
            float4 av = *(const float4*)&As[k][ty*4];
            float4 bv = *(const float4*)&Bs[k][tx*4];
            acc[0][0] = fmaf(av.x, bv.x, acc[0][0]); acc[0][1] = fmaf(av.x, bv.y, acc[0][1]);
            acc[0][2] = fmaf(av.x, bv.z, acc[0][2]); acc[0][3] = fmaf(av.x, bv.w, acc[0][3]);
            acc[1][0] = fmaf(av.y, bv.x, acc[1][0]); acc[1][1] = fmaf(av.y, bv.y, acc[1][1]);
            acc[1][2] = fmaf(av.y, bv.z, acc[1][2]); acc[1][3] = fmaf(av.y, bv.w, acc[1][3]);
            acc[2][0] = fmaf(av.z, bv.x, acc[2][0]); acc[2][1] = fmaf(av.z, bv.y, acc[2][1]);
            acc[2][2] = fmaf(av.z, bv.z, acc[2][2]); acc[2][3] = fmaf(av.z, bv.w, acc[2][3]);
            acc[3][0] = fmaf(av.w, bv.x, acc[3][0]); acc[3][1] = fmaf(av.w, bv.y, acc[3][1]);
            acc[3][2] = fmaf(av.w, bv.z, acc[3][2]); acc[3][3] = fmaf(av.w, bv.w, acc[3][3]);
        }
        __syncthreads();
    }

    float* dst = (mode == 0) ? g_HP : (mode == 1) ? g_HP2 :
                 (mode == 2) ? g_CP : g_P;
#pragma unroll
    for (int i = 0; i < 4; i++) {
        int rg = r0 + ty*4 + i;
#pragma unroll
        for (int j = 0; j < 4; j++) {
            int jg = c0 + tx*4 + j;
            if (jg < ncols) dst[rg*ncols + jg] = acc[i][j];
        }
    }
}

// ---------------- gate + memory-update job (block handles batch b) ----------------
__device__ __forceinline__ void gate_job(
    int b, int t,
    const float* __restrict__ hs, const float* __restrict__ mask,
    const float* __restrict__ be1, const float* __restrict__ We2,
    const float* __restrict__ be2, const float* __restrict__ bs1,
    const float* __restrict__ Ws2, const float* __restrict__ bs2,
    const float* __restrict__ Ws1, const float* __restrict__ bu,
    float* __restrict__ out,
    float (&s_sim)[MCELLS], float (&s_usage)[MCELLS],
    float (&s_indv)[MCELLS], float (&s_ow)[MCELLS],
    float (&s_red)[8], float &s_ent)
{
    const int tid = threadIdx.x;
    const int warp = tid >> 5, lane = tid & 31;

    const float* hb = hs + ((size_t)t*BATCH + b) * HDIM;
    const float* P  = g_P + b*900;
    const float* wu_row = Ws1 + 900*300;   // usage-feature row of Ws1

    if (tid < MCELLS) s_usage[tid] = g_usage[b*MCELLS + tid];
    __syncthreads();

    // ---- entity prob ----
    float acc = 0.f;
    for (int j = tid; j < 300; j += NTHREADS)
        acc += fmaxf(P[j] + be1[j], 0.f) * We2[j];
    acc = warpSum(acc);
    if (lane == 0) s_red[warp] = acc;
    __syncthreads();
    if (tid == 0) {
        float s = 0.f;
        for (int w = 0; w < 8; w++) s += s_red[w];
        float score = s + be2[0];
        float sig = 1.f / (1.f + expf(-score));
        s_ent = sig * mask[(size_t)t*BATCH + b];
    }

    // ---- sim[m] ----
    for (int m = warp; m < MCELLS; m += 8) {
        float u = s_usage[m];
        const float* HPr  = g_HP  + (b*MCELLS + m)*300;
        const float* HP2r = g_HP2 + (b*MCELLS + m)*300;
        float a = 0.f;
        for (int j = lane; j < 300; j += 32)
            a += fmaxf(HPr[j] + HP2r[j] + P[300 + j] + u*wu_row[j] + bs1[j], 0.f)
                 * Ws2[j];
        a = warpSum(a);
        if (lane == 0) s_sim[m] = a + bs2[0];
    }
    __syncthreads();

    // ---- gating (warp 0; lane = slot 0..20) ----
    if (warp == 0) {
        const unsigned FULL = 0xffffffffu;
        const int m = lane;
        const float NEG_INF = -INFINITY;
        float usg  = (m < MCELLS) ? s_usage[m] : 0.f;
        float simv = (m < MCELLS) ? s_sim[m]   : 0.f;

        float comb;
        if (m < MCELLS)       comb = (usg > 0.f) ? simv : -10000.f;
        else if (m == MCELLS) comb = 0.f;
        else                  comb = NEG_INF;
        float mx   = warpMax(comb);
        float ex   = (m <= MCELLS) ? expf(comb - mx) : 0.f;
        float esum = warpSum(ex);
        float prob = ex / esum;
        float mult = (m < MCELLS) ? ((usg > 0.f) ? 1.f : 0.f)
                                  : ((m == MCELLS) ? 1.f : 0.f);
        float maskedp = prob * mult;
        float msum = warpSum(maskedp);
        float nrm  = maskedp / (msum + EPS_V);
        float co   = s_ent * nrm;
        float ow_base = __shfl_sync(FULL, co, MCELLS);
        float indv = (m < MCELLS) ? co : 0.f;

        float s2  = (m < MCELLS) ? simv : NEG_INF;
        float mx2 = warpMax(s2);
        float e2  = (m < MCELLS) ? expf(simv - mx2) : 0.f;
        float es2 = warpSum(e2);
        float nsim = e2 / es2;

        float ow_score = (m < MCELLS)
            ? ((usg == 0.f ? nsim * 100000.f : 0.f) + (1.f - usg))
            : NEG_INF;
        float maxv = warpMax(ow_score);
        float nz   = (m < MCELLS && ow_score == maxv)
            ? jax_noise((unsigned)(((size_t)t*BATCH + b)*MCELLS + m)) : 0.f;
        float nzmax = warpMax(nz);
        unsigned ballot = __ballot_sync(FULL, (m < MCELLS) && (nz == nzmax));
        int idx = __ffs(ballot) - 1;

        float ow = (m == idx) ? ow_base : 0.f;
        float nu = fminf(1.f, ow + indv + DECAY * usg);

        float* out_ent = out;
        float* out_usg = out + (size_t)T_STEPS*BATCH;
        float* out_crf = out_usg + (size_t)T_STEPS*BATCH*MCELLS;
        float* out_ow  = out_crf + (size_t)T_STEPS*BATCH*MCELLS;
        if (m < MCELLS) {
            s_indv[m] = indv;
            s_ow[m]   = ow;
            g_usage[b*MCELLS + m] = nu;
            size_t o = ((size_t)t*BATCH + b)*MCELLS + m;
            out_usg[o] = nu;
            out_crf[o] = indv * (1.f - EPS_V) + EPS_V;
            out_ow[o]  = ow   * (1.f - EPS_V) + EPS_V;
        }
        if (m == 0)
            out_ent[(size_t)t*BATCH + b] = s_ent * (1.f - EPS_V) + EPS_V;
    }
    __syncthreads();

    // ---- memory update ----
    for (int m = 0; m < MCELLS; m++) {
        float owv = s_ow[m], iv = s_indv[m];
        float coef = 1.f - owv - iv;
        float* memr = g_mem + (b*MCELLS + m)*300;
        const float* CPr = g_CP + (b*MCELLS + m)*300;
        for (int j = tid; j < 300; j += NTHREADS) {
            float c = tanhf(CPr[j] + P[600 + j] + bu[j]);
            memr[j] = owv*hb[j] + coef*memr[j] + iv*c;
        }
    }
}

// ---------------- persistent kernel ----------------
__global__ __launch_bounds__(NTHREADS, 2) void k_persist(
    const float* __restrict__ hs, const float* __restrict__ mask,
    const float* __restrict__ We1, const float* __restrict__ be1,
    const float* __restrict__ We2, const float* __restrict__ be2,
    const float* __restrict__ Ws1, const float* __restrict__ bs1,
    const float* __restrict__ Ws2, const float* __restrict__ bs2,
    const float* __restrict__ Wu,  const float* __restrict__ bu,
    float* __restrict__ out)
{
    __shared__ float As[BK][BM+4];
    __shared__ float Bs[BK][BN];
    __shared__ float s_sim[MCELLS], s_usage[MCELLS], s_indv[MCELLS], s_ow[MCELLS];
    __shared__ float s_red[8];
    __shared__ float s_ent;
    __shared__ int s_job;

    unsigned target = 0;
    for (int t = 0; t < T_STEPS; t++) {
        // phase A: GEMMs, dynamically balanced
        for (;;) {
            if (threadIdx.x == 0)
                s_job = (int)atomicAdd(&g_jobctr[t], 1u);
            __syncthreads();
            int job = s_job;
            if (job >= NJOBS) break;
            gemm_job(job, t, hs, We1, Ws1, Wu, As, Bs);
        }
        grid_bar(target);
        // phase B: gate + memory update
        if (blockIdx.x < BATCH)
            gate_job(blockIdx.x, t, hs, mask, be1, We2, be2, bs1, Ws2, bs2,
                     Ws1, bu, out, s_sim, s_usage, s_indv, s_ow, s_red, s_ent);
        grid_bar(target);
    }
}

extern "C" void kernel_launch(void* const* d_in, const int* in_sizes, int n_in,
                              void* d_out, int out_size) {
    const float* hs   = (const float*)d_in[0];
    const float* mask = (const float*)d_in[1];
    const float* We1  = (const float*)d_in[2];
    const float* be1  = (const float*)d_in[3];
    const float* We2  = (const float*)d_in[4];
    const float* be2  = (const float*)d_in[5];
    const float* Ws1  = (const float*)d_in[6];
    const float* bs1  = (const float*)d_in[7];
    const float* Ws2  = (const float*)d_in[8];
    const float* bs2  = (const float*)d_in[9];
    const float* Wu   = (const float*)d_in[10];
    const float* bu   = (const float*)d_in[11];
    float* out = (float*)d_out;

    void *pmem, *pusg, *pcnt, *pjob;
    cudaGetSymbolAddress(&pmem, g_mem);
    cudaGetSymbolAddress(&pusg, g_usage);
    cudaGetSymbolAddress(&pcnt, g_count);
    cudaGetSymbolAddress(&pjob, g_jobctr);
    cudaMemsetAsync(pmem, 0, sizeof(float)*(size_t)ROWS*HDIM);
    cudaMemsetAsync(pusg, 0, sizeof(float)*(size_t)ROWS);
    cudaMemsetAsync(pcnt, 0, sizeof(unsigned));
    cudaMemsetAsync(pjob, 0, sizeof(unsigned)*T_STEPS);

    k_persist<<<NBLOCKS, NTHREADS>>>(hs, mask, We1, be1, We2, be2,
                                     Ws1, bs1, Ws2, bs2, Wu, bu, out);
}

// round 5
// speedup vs baseline: 2.3066x; 1.4110x over previous
#include <cuda_runtime.h>
#include <math.h>

// ---------------- problem constants ----------------
#define T_STEPS 512
#define BATCH   128
#define HDIM    300
#define MCELLS  20
#define ROWS    (BATCH*MCELLS)   // 2560
#define DECAY   0.98f
#define EPS_V   1e-8f

#define NTHREADS 256
#define NJOBS    1260  // (3 matrices * 40rt*5ct + P 2rt*15ct) * 2 K-halves

// 1 = JAX >= 0.4.30 default (threefry_partitionable)
#define THREEFRY_PARTITIONABLE 1

// ---------------- device state (no allocation anywhere) ----------------
__device__ float g_mem[ROWS*HDIM];      // (B,M,H)
__device__ float g_usage[ROWS];         // (B,M)
__device__ float g_HPa [ROWS*HDIM];     // mem@Ws1[0:300], K 0..140
__device__ float g_HPb [ROWS*HDIM];     // mem@Ws1[0:300], K 140..300
__device__ float g_HP2a[ROWS*HDIM];     // (h*mem)@Ws1[600:900] halves
__device__ float g_HP2b[ROWS*HDIM];
__device__ float g_CPa [ROWS*HDIM];     // mem@Wu[300:600] halves
__device__ float g_CPb [ROWS*HDIM];
__device__ float g_Pa[BATCH*900];       // h@[We1|Ws1(300:600)|Wu(0:300)] halves
__device__ float g_Pb[BATCH*900];
__device__ float g_ow[ROWS];            // gating outputs for phase C
__device__ float g_indv[ROWS];
__device__ unsigned g_count;            // grid-barrier counter
__device__ unsigned g_jobctr[T_STEPS];  // per-step dynamic job counters

// ---------------- software grid barrier ----------------
__device__ __forceinline__ void grid_bar(unsigned &target, int nblk) {
    __syncthreads();
    if (threadIdx.x == 0) {
        target += (unsigned)nblk;
        __threadfence();
        atomicAdd(&g_count, 1u);
        volatile unsigned* p = &g_count;
        while (*p < target) { }
        __threadfence();
    }
    __syncthreads();
}

// ---------------- JAX threefry-2x32-20 noise ----------------
__device__ __forceinline__ void tf_round(unsigned &x0, unsigned &x1, int r) {
    x0 += x1;
    x1 = (x1 << r) | (x1 >> (32 - r));
    x1 ^= x0;
}
__device__ __forceinline__ void threefry2x32(unsigned c0, unsigned c1,
                                             unsigned &o0, unsigned &o1) {
    const unsigned k0 = 0u, k1 = 42u, k2 = 0x1BD11BDAu ^ 0u ^ 42u;
    unsigned x0 = c0 + k0, x1 = c1 + k1;
    tf_round(x0,x1,13); tf_round(x0,x1,15); tf_round(x0,x1,26); tf_round(x0,x1,6);
    x0 += k1; x1 += k2 + 1u;
    tf_round(x0,x1,17); tf_round(x0,x1,29); tf_round(x0,x1,16); tf_round(x0,x1,24);
    x0 += k2; x1 += k0 + 2u;
    tf_round(x0,x1,13); tf_round(x0,x1,15); tf_round(x0,x1,26); tf_round(x0,x1,6);
    x0 += k0; x1 += k1 + 3u;
    tf_round(x0,x1,17); tf_round(x0,x1,29); tf_round(x0,x1,16); tf_round(x0,x1,24);
    x0 += k1; x1 += k2 + 4u;
    tf_round(x0,x1,13); tf_round(x0,x1,15); tf_round(x0,x1,26); tf_round(x0,x1,6);
    x0 += k2; x1 += k0 + 5u;
    o0 = x0; o1 = x1;
}
__device__ __forceinline__ float jax_noise(unsigned i) {
    unsigned bits;
#if THREEFRY_PARTITIONABLE
    unsigned o0, o1;
    threefry2x32(0u, i, o0, o1);
    bits = o0 ^ o1;
#else
    const unsigned half = (unsigned)(T_STEPS*BATCH*MCELLS) / 2u;
    unsigned o0, o1;
    if (i < half) { threefry2x32(i, i + half, o0, o1); bits = o0; }
    else          { threefry2x32(i - half, i, o0, o1); bits = o1; }
#endif
    float f = __uint_as_float((bits >> 9) | 0x3f800000u) - 1.0f;
    float u = __fadd_rn(__fmul_rn(f, 0.99f), 0.01f);
    return fmaxf(0.01f, u);
}

// ---------------- warp reductions ----------------
__device__ __forceinline__ float warpSum(float v) {
#pragma unroll
    for (int o = 16; o; o >>= 1) v += __shfl_xor_sync(0xffffffffu, v, o);
    return v;
}
__device__ __forceinline__ float warpMax(float v) {
#pragma unroll
    for (int o = 16; o; o >>= 1) v = fmaxf(v, __shfl_xor_sync(0xffffffffu, v, o));
    return v;
}

// fast accurate-enough tanh: abs err ~1e-6; __expf(inf)->inf gives exact saturation
__device__ __forceinline__ float tanh_fast(float x) {
    float ax = fabsf(x);
    float e  = __expf(2.0f * ax);
    float r  = 1.0f - __fdividef(2.0f, e + 1.0f);
    return copysignf(r, x);
}

// ---------------- GEMM tile job ----------------
// 1260 jobs. job<1200: mtype=job/400 (0=HP 1=HP2 2=CP), e=job%400, kh=e&1,
//   e2=e>>1: r0=(e2/5)*64 (2560 rows), c0=(e2%5)*64 (300 cols).
// job>=1200: P: e=job-1200, kh=e&1, e2=e>>1: r0=(e2/15)*64 (128 rows),
//   c0=(e2%15)*64 (900 cols).
// K-half: kh=0 -> K[0,140) 7 tiles; kh=1 -> K[140,300) 8 tiles.
#define BM 64
#define BN 64
#define BK 20

__device__ __forceinline__ void gemm_job(
    int job, int t,
    const float* __restrict__ hs, const float* __restrict__ We1,
    const float* __restrict__ Ws1, const float* __restrict__ Wu,
    float (&As)[2][BK][BM+4], float (&Bs)[2][BK][BN])
{
    const int tid = threadIdx.x;
    const float* hbase = hs + (size_t)t * BATCH * HDIM;

    int mtype, r0, c0, kh, ncols;
    if (job < 1200) {
        mtype = job / 400;
        int e = job % 400;  kh = e & 1;  int e2 = e >> 1;
        r0 = (e2 / 5) * BM;  c0 = (e2 % 5) * BN;  ncols = 300;
    } else {
        mtype = 3;
        int e = job - 1200; kh = e & 1;  int e2 = e >> 1;
        r0 = (e2 / 15) * BM; c0 = (e2 % 15) * BN; ncols = 900;
    }
    const int kstart = kh ? 140 : 0;
    const int ntiles = kh ? 8 : 7;

    const int tx = tid & 15;
    const int ty = tid >> 4;
    float acc[4][4];
#pragma unroll
    for (int i = 0; i < 4; i++)
#pragma unroll
        for (int j = 0; j < 4; j++) acc[i][j] = 0.f;

    float ra[5], rb[5];

    // ---- staged loaders ----
    auto loadA = [&](int kt) {
#pragma unroll
        for (int i = 0; i < 5; i++) {
            int idx = tid + i*NTHREADS;
            int r = idx / BK, k = idx - (idx / BK) * BK;
            int rg = r0 + r, kg = kstart + kt*BK + k;
            float v;
            if (mtype == 0 || mtype == 2) v = g_mem[rg*HDIM + kg];
            else if (mtype == 1)          v = g_mem[rg*HDIM + kg] *
                                              hbase[(rg/MCELLS)*HDIM + kg];
            else                          v = hbase[rg*HDIM + kg];
            ra[i] = v;
        }
    };
    auto loadB = [&](int kt) {
#pragma unroll
        for (int i = 0; i < 5; i++) {
            int idx = tid + i*NTHREADS;
            int k = idx >> 6, j = idx & 63;
            int kg = kstart + kt*BK + k, jg = c0 + j;
            float v = 0.f;
            if (jg < ncols) {
                if (mtype == 0)      v = Ws1[kg*300 + jg];
                else if (mtype == 1) v = Ws1[(kg + 600)*300 + jg];
                else if (mtype == 2) v = Wu[(kg + 300)*300 + jg];
                else {
                    int role = jg / 300, jc = jg - role*300;
                    if (role == 0)      v = We1[kg*300 + jc];
                    else if (role == 1) v = Ws1[(kg + 300)*300 + jc];
                    else                v = Wu[kg*300 + jc];
                }
            }
            rb[i] = v;
        }
    };
    auto storeTiles = [&](int buf) {
#pragma unroll
        for (int i = 0; i < 5; i++) {
            int idx = tid + i*NTHREADS;
            int r = idx / BK, k = idx - (idx / BK) * BK;
            As[buf][k][r] = ra[i];
        }
#pragma unroll
        for (int i = 0; i < 5; i++) {
            int idx = tid + i*NTHREADS;
            int k = idx >> 6, j = idx & 63;
            Bs[buf][k][j] = rb[i];
        }
    };

    // prologue
    loadA(0); loadB(0);
    storeTiles(0);
    __syncthreads();

    for (int kt = 0; kt < ntiles; kt++) {
        int cur = kt & 1;
        if (kt + 1 < ntiles) { loadA(kt + 1); loadB(kt + 1); }
#pragma unroll
        for (int k = 0; k < BK; k++) {
            float4 av = *(const float4*)&As[cur][k][ty*4];
            float4 bv = *(const float4*)&Bs[cur][k][tx*4];
            acc[0][0] = fmaf(av.x, bv.x, acc[0][0]); acc[0][1] = fmaf(av.x, bv.y, acc[0][1]);
            acc[0][2] = fmaf(av.x, bv.z, acc[0][2]); acc[0][3] = fmaf(av.x, bv.w, acc[0][3]);
            acc[1][0] = fmaf(av.y, bv.x, acc[1][0]); acc[1][1] = fmaf(av.y, bv.y, acc[1][1]);
            acc[1][2] = fmaf(av.y, bv.z, acc[1][2]); acc[1][3] = fmaf(av.y, bv.w, acc[1][3]);
            acc[2][0] = fmaf(av.z, bv.x, acc[2][0]); acc[2][1] = fmaf(av.z, bv.y, acc[2][1]);
            acc[2][2] = fmaf(av.z, bv.z, acc[2][2]); acc[2][3] = fmaf(av.z, bv.w, acc[2][3]);
            acc[3][0] = fmaf(av.w, bv.x, acc[3][0]); acc[3][1] = fmaf(av.w, bv.y, acc[3][1]);
            acc[3][2] = fmaf(av.w, bv.z, acc[3][2]); acc[3][3] = fmaf(av.w, bv.w, acc[3][3]);
        }
        if (kt + 1 < ntiles) storeTiles(cur ^ 1);
        __syncthreads();
    }

    float* dst;
    if (mtype == 0)      dst = kh ? g_HPb  : g_HPa;
    else if (mtype == 1) dst = kh ? g_HP2b : g_HP2a;
    else if (mtype == 2) dst = kh ? g_CPb  : g_CPa;
    else                 dst = kh ? g_Pb   : g_Pa;
#pragma unroll
    for (int i = 0; i < 4; i++) {
        int rg = r0 + ty*4 + i;
#pragma unroll
        for (int j = 0; j < 4; j++) {
            int jg = c0 + tx*4 + j;
            if (jg < ncols) dst[rg*ncols + jg] = acc[i][j];
        }
    }
}

// ---------------- gating job (block handles batch b; no mem update) ----------------
__device__ __forceinline__ void gate_job(
    int b, int t,
    const float* __restrict__ hs, const float* __restrict__ mask,
    const float* __restrict__ be1, const float* __restrict__ We2,
    const float* __restrict__ be2, const float* __restrict__ bs1,
    const float* __restrict__ Ws2, const float* __restrict__ bs2,
    const float* __restrict__ Ws1,
    float* __restrict__ out,
    float (&s_sim)[MCELLS], float (&s_usage)[MCELLS],
    float (&s_red)[8], float &s_ent)
{
    const int tid = threadIdx.x;
    const int warp = tid >> 5, lane = tid & 31;

    const float* Pa = g_Pa + b*900;
    const float* Pb = g_Pb + b*900;
    const float* wu_row = Ws1 + 900*300;

    if (tid < MCELLS) s_usage[tid] = g_usage[b*MCELLS + tid];
    __syncthreads();

    // ---- entity prob ----
    float acc = 0.f;
    for (int j = tid; j < 300; j += NTHREADS)
        acc += fmaxf(Pa[j] + Pb[j] + be1[j], 0.f) * We2[j];
    acc = warpSum(acc);
    if (lane == 0) s_red[warp] = acc;
    __syncthreads();
    if (tid == 0) {
        float s = 0.f;
        for (int w = 0; w < 8; w++) s += s_red[w];
        float score = s + be2[0];
        float sig = 1.f / (1.f + expf(-score));
        s_ent = sig * mask[(size_t)t*BATCH + b];
    }

    // ---- sim[m] ----
    for (int m = warp; m < MCELLS; m += 8) {
        float u = s_usage[m];
        const int ro = (b*MCELLS + m)*300;
        float a = 0.f;
        for (int j = lane; j < 300; j += 32) {
            float pre = g_HPa[ro+j] + g_HPb[ro+j] + g_HP2a[ro+j] + g_HP2b[ro+j]
                      + Pa[300 + j] + Pb[300 + j] + u*wu_row[j] + bs1[j];
            a += fmaxf(pre, 0.f) * Ws2[j];
        }
        a = warpSum(a);
        if (lane == 0) s_sim[m] = a + bs2[0];
    }
    __syncthreads();

    // ---- gating (warp 0; lane = slot 0..20) ----
    if (warp == 0) {
        const unsigned FULL = 0xffffffffu;
        const int m = lane;
        const float NEG_INF = -INFINITY;
        float usg  = (m < MCELLS) ? s_usage[m] : 0.f;
        float simv = (m < MCELLS) ? s_sim[m]   : 0.f;

        float comb;
        if (m < MCELLS)       comb = (usg > 0.f) ? simv : -10000.f;
        else if (m == MCELLS) comb = 0.f;
        else                  comb = NEG_INF;
        float mx   = warpMax(comb);
        float ex   = (m <= MCELLS) ? expf(comb - mx) : 0.f;
        float esum = warpSum(ex);
        float prob = ex / esum;
        float mult = (m < MCELLS) ? ((usg > 0.f) ? 1.f : 0.f)
                                  : ((m == MCELLS) ? 1.f : 0.f);
        float maskedp = prob * mult;
        float msum = warpSum(maskedp);
        float nrm  = maskedp / (msum + EPS_V);
        float co   = s_ent * nrm;
        float ow_base = __shfl_sync(FULL, co, MCELLS);
        float indv = (m < MCELLS) ? co : 0.f;

        float s2  = (m < MCELLS) ? simv : NEG_INF;
        float mx2 = warpMax(s2);
        float e2  = (m < MCELLS) ? expf(simv - mx2) : 0.f;
        float es2 = warpSum(e2);
        float nsim = e2 / es2;

        float ow_score = (m < MCELLS)
            ? ((usg == 0.f ? nsim * 100000.f : 0.f) + (1.f - usg))
            : NEG_INF;
        float maxv = warpMax(ow_score);
        float nz   = (m < MCELLS && ow_score == maxv)
            ? jax_noise((unsigned)(((size_t)t*BATCH + b)*MCELLS + m)) : 0.f;
        float nzmax = warpMax(nz);
        unsigned ballot = __ballot_sync(FULL, (m < MCELLS) && (nz == nzmax));
        int idx = __ffs(ballot) - 1;

        float ow = (m == idx) ? ow_base : 0.f;
        float nu = fminf(1.f, ow + indv + DECAY * usg);

        float* out_ent = out;
        float* out_usg = out + (size_t)T_STEPS*BATCH;
        float* out_crf = out_usg + (size_t)T_STEPS*BATCH*MCELLS;
        float* out_ow  = out_crf + (size_t)T_STEPS*BATCH*MCELLS;
        if (m < MCELLS) {
            g_ow[b*MCELLS + m]   = ow;
            g_indv[b*MCELLS + m] = indv;
            g_usage[b*MCELLS + m] = nu;
            size_t o = ((size_t)t*BATCH + b)*MCELLS + m;
            out_usg[o] = nu;
            out_crf[o] = indv * (1.f - EPS_V) + EPS_V;
            out_ow[o]  = ow   * (1.f - EPS_V) + EPS_V;
        }
        if (m == 0)
            out_ent[(size_t)t*BATCH + b] = s_ent * (1.f - EPS_V) + EPS_V;
    }
}

// ---------------- persistent kernel ----------------
__global__ __launch_bounds__(NTHREADS, 2) void k_persist(
    const float* __restrict__ hs, const float* __restrict__ mask,
    const float* __restrict__ We1, const float* __restrict__ be1,
    const float* __restrict__ We2, const float* __restrict__ be2,
    const float* __restrict__ Ws1, const float* __restrict__ bs1,
    const float* __restrict__ Ws2, const float* __restrict__ bs2,
    const float* __restrict__ Wu,  const float* __restrict__ bu,
    float* __restrict__ out, int nblk)
{
    __shared__ float As[2][BK][BM+4];
    __shared__ float Bs[2][BK][BN];
    __shared__ float s_sim[MCELLS], s_usage[MCELLS];
    __shared__ float s_red[8];
    __shared__ float s_ent;
    __shared__ int s_job;

    const int tid = threadIdx.x;
    unsigned target = 0;

    for (int t = 0; t < T_STEPS; t++) {
        // ---- phase A: GEMMs (dynamic) ----
        for (;;) {
            if (tid == 0) s_job = (int)atomicAdd(&g_jobctr[t], 1u);
            __syncthreads();
            int job = s_job;
            __syncthreads();
            if (job >= NJOBS) break;
            gemm_job(job, t, hs, We1, Ws1, Wu, As, Bs);
        }
        grid_bar(target, nblk);

        // ---- phase B: gating (128 blocks) ----
        if (blockIdx.x < BATCH)
            gate_job(blockIdx.x, t, hs, mask, be1, We2, be2, bs1, Ws2, bs2,
                     Ws1, out, s_sim, s_usage, s_red, s_ent);
        grid_bar(target, nblk);

        // ---- phase C: mem update (all blocks, float4) ----
        {
            const float4* hb4 = (const float4*)(hs + (size_t)t*BATCH*HDIM);
            const float4* Pa4 = (const float4*)g_Pa;
            const float4* Pb4 = (const float4*)g_Pb;
            const float4* CPa4 = (const float4*)g_CPa;
            const float4* CPb4 = (const float4*)g_CPb;
            const float4* bu4 = (const float4*)bu;
            float4* mem4 = (float4*)g_mem;
            const int total = ROWS * 75;   // 75 float4 per 300-row
            for (int idx = blockIdx.x*NTHREADS + tid; idx < total;
                 idx += nblk*NTHREADS) {
                int r  = idx / 75;
                int jq = idx - r*75;
                int b  = r / MCELLS;
                float owv = g_ow[r], iv = g_indv[r];
                float coef = 1.f - owv - iv;
                float4 cp = CPa4[idx], cpb = CPb4[idx];
                float4 p6 = Pa4[b*225 + 150 + jq], p6b = Pb4[b*225 + 150 + jq];
                float4 bv = bu4[jq];
                float4 h  = hb4[b*75 + jq];
                float4 mo = mem4[idx];
                float4 res;
                res.x = owv*h.x + coef*mo.x + iv*tanh_fast(cp.x + cpb.x + p6.x + p6b.x + bv.x);
                res.y = owv*h.y + coef*mo.y + iv*tanh_fast(cp.y + cpb.y + p6.y + p6b.y + bv.y);
                res.z = owv*h.z + coef*mo.z + iv*tanh_fast(cp.z + cpb.z + p6.z + p6b.z + bv.z);
                res.w = owv*h.w + coef*mo.w + iv*tanh_fast(cp.w + cpb.w + p6.w + p6b.w + bv.w);
                mem4[idx] = res;
            }
        }
        grid_bar(target, nblk);
    }
}

extern "C" void kernel_launch(void* const* d_in, const int* in_sizes, int n_in,
                              void* d_out, int out_size) {
    const float* hs   = (const float*)d_in[0];
    const float* mask = (const float*)d_in[1];
    const float* We1  = (const float*)d_in[2];
    const float* be1  = (const float*)d_in[3];
    const float* We2  = (const float*)d_in[4];
    const float* be2  = (const float*)d_in[5];
    const float* Ws1  = (const float*)d_in[6];
    const float* bs1  = (const float*)d_in[7];
    const float* Ws2  = (const float*)d_in[8];
    const float* bs2  = (const float*)d_in[9];
    const float* Wu   = (const float*)d_in[10];
    const float* bu   = (const float*)d_in[11];
    float* out = (float*)d_out;

    int smcount = 148;
    cudaDeviceGetAttribute(&smcount, cudaDevAttrMultiProcessorCount, 0);
    int nblk = 2 * smcount;

    void *pmem, *pusg, *pcnt, *pjob;
    cudaGetSymbolAddress(&pmem, g_mem);
    cudaGetSymbolAddress(&pusg, g_usage);
    cudaGetSymbolAddress(&pcnt, g_count);
    cudaGetSymbolAddress(&pjob, g_jobctr);
    cudaMemsetAsync(pmem, 0, sizeof(float)*(size_t)ROWS*HDIM);
    cudaMemsetAsync(pusg, 0, sizeof(float)*(size_t)ROWS);
    cudaMemsetAsync(pcnt, 0, sizeof(unsigned));
    cudaMemsetAsync(pjob, 0, sizeof(unsigned)*T_STEPS);

    k_persist<<<nblk, NTHREADS>>>(hs, mask, We1, be1, We2, be2,
                                  Ws1, bs1, Ws2, bs2, Wu, bu, out, nblk);
}